// round 6
// baseline (speedup 1.0000x reference)
#include <cuda_runtime.h>
#include <cuda_fp16.h>
#include <math_constants.h>

// ---------------------------------------------------------------------------
// Problem constants
// ---------------------------------------------------------------------------
#define NN 8192
#define CC 256
#define TM 128                  // CTA rows
#define TNT 128                 // CTA col-tile width
#define NSPLIT 4
#define CPS (NN / NSPLIT)       // 2048 cols per CTA
#define NTILE (CPS / TNT)       // 16 col tiles
#define KCH 64                  // k per chunk
#define NCHUNKS (NTILE * 4)     // 64 chunk steps
#define NCTAS (NSPLIT * (NN / TM))   // 256
#define INV_T 14.285714285714285714f
#define LN2 0.6931471805599453f
// sqrt(INV_T * log2(e)) folded into fp16 operands: acc = logit * log2(e)
#define SCALE 4.5398160052f

// SMEM layout (dynamic)
#define A_STRIDE 528            // 256 halves + 8 pad
#define B_STRIDE 144            // 64 halves + 8 pad
#define SA 0
#define SA_BYTES (TM * A_STRIDE)            // 67584
#define SB (SA + SA_BYTES)
#define SB_STAGE (TNT * B_STRIDE)           // 18432
#define SRED_M (SB + 2 * SB_STAGE)          // 104448
#define SRED_S (SRED_M + TM * 2 * 4)        // +1024
#define SM_TOTAL (SRED_S + TM * 2 * 4)      // 106496  (x2 CTAs = 212992 < 228KB)

typedef unsigned int u32;

// ---------------------------------------------------------------------------
// Device globals (no allocation allowed)
// ---------------------------------------------------------------------------
__device__ __align__(16) __half g_qh[NN * CC];
__device__ __align__(16) __half g_kh[NN * CC];
__device__ float g_pm[NN * NSPLIT];
__device__ float g_ps[NN * NSPLIT];
__device__ float g_pos[NN];
__device__ unsigned int g_ticket;   // zero-initialized; reset by last CTA

// ---------------------------------------------------------------------------
// PTX helpers (base ISA only; must compile for compute_103 non-'a')
// ---------------------------------------------------------------------------
__device__ __forceinline__ u32 smem_u32(const void* p) {
    u32 a;
    asm("{ .reg .u64 t; cvta.to.shared.u64 t, %1; cvt.u32.u64 %0, t; }" : "=r"(a) : "l"(p));
    return a;
}
__device__ __forceinline__ void cp_async16(u32 dst, const void* src) {
    asm volatile("cp.async.cg.shared.global [%0], [%1], 16;" :: "r"(dst), "l"(src));
}
__device__ __forceinline__ void cp_commit() {
    asm volatile("cp.async.commit_group;" ::: "memory");
}
__device__ __forceinline__ void cp_wait0() {
    asm volatile("cp.async.wait_group 0;" ::: "memory");
}
__device__ __forceinline__ void cp_wait1() {
    asm volatile("cp.async.wait_group 1;" ::: "memory");
}
__device__ __forceinline__ void ldsm_x4(u32& r0, u32& r1, u32& r2, u32& r3, u32 addr) {
    asm volatile("ldmatrix.sync.aligned.m8n8.x4.shared.b16 {%0,%1,%2,%3}, [%4];"
                 : "=r"(r0), "=r"(r1), "=r"(r2), "=r"(r3) : "r"(addr));
}
__device__ __forceinline__ void mma16816(float& d0, float& d1, float& d2, float& d3,
                                         u32 a0, u32 a1, u32 a2, u32 a3,
                                         u32 b0, u32 b1) {
    asm volatile("mma.sync.aligned.m16n8k16.row.col.f32.f16.f16.f32 "
                 "{%0,%1,%2,%3}, {%4,%5,%6,%7}, {%8,%9}, {%0,%1,%2,%3};"
                 : "+f"(d0), "+f"(d1), "+f"(d2), "+f"(d3)
                 : "r"(a0), "r"(a1), "r"(a2), "r"(a3), "r"(b0), "r"(b1));
}

// ---------------------------------------------------------------------------
// Fused convert (fp32 -> scaled fp16) + diagonal dot. One warp per row.
// Front-batched loads (MLP=4) — kernel is DRAM-latency bound.
// ---------------------------------------------------------------------------
__global__ void convert_pos_kernel(const float* __restrict__ q, const float* __restrict__ k) {
    const int row = (blockIdx.x * blockDim.x + threadIdx.x) >> 5;
    const int lane = threadIdx.x & 31;
    const float4* q4 = (const float4*)(q + (size_t)row * CC);
    const float4* k4 = (const float4*)(k + (size_t)row * CC);
    const float4 a0 = q4[lane];
    const float4 a1 = q4[lane + 32];
    const float4 b0 = k4[lane];
    const float4 b1 = k4[lane + 32];

    float dot = (a0.x * b0.x + a0.y * b0.y) + (a0.z * b0.z + a0.w * b0.w)
              + (a1.x * b1.x + a1.y * b1.y) + (a1.z * b1.z + a1.w * b1.w);

    uint2 o;
    __half2 h;
    h = __floats2half2_rn(a0.x * SCALE, a0.y * SCALE); o.x = *(u32*)&h;
    h = __floats2half2_rn(a0.z * SCALE, a0.w * SCALE); o.y = *(u32*)&h;
    ((uint2*)g_qh)[(size_t)row * (CC / 4) + lane] = o;
    h = __floats2half2_rn(a1.x * SCALE, a1.y * SCALE); o.x = *(u32*)&h;
    h = __floats2half2_rn(a1.z * SCALE, a1.w * SCALE); o.y = *(u32*)&h;
    ((uint2*)g_qh)[(size_t)row * (CC / 4) + lane + 32] = o;
    h = __floats2half2_rn(b0.x * SCALE, b0.y * SCALE); o.x = *(u32*)&h;
    h = __floats2half2_rn(b0.z * SCALE, b0.w * SCALE); o.y = *(u32*)&h;
    ((uint2*)g_kh)[(size_t)row * (CC / 4) + lane] = o;
    h = __floats2half2_rn(b1.x * SCALE, b1.y * SCALE); o.x = *(u32*)&h;
    h = __floats2half2_rn(b1.z * SCALE, b1.w * SCALE); o.y = *(u32*)&h;
    ((uint2*)g_kh)[(size_t)row * (CC / 4) + lane + 32] = o;

#pragma unroll
    for (int off = 16; off; off >>= 1)
        dot += __shfl_xor_sync(0xFFFFFFFFu, dot, off);
    if (lane == 0) g_pos[row] = dot * INV_T;
}

// ---------------------------------------------------------------------------
// Main: HMMA fp16 GEMM fused with online row LSE (log2 domain) + final
// combine done by the last CTA to finish (ticket).
// grid = (NSPLIT=4, 64) = 256 CTAs, 256 threads, 2 CTAs/SM.
// ---------------------------------------------------------------------------
extern __shared__ char smem[];

__global__ __launch_bounds__(256, 2)
void sim_lse_hmma_kernel(float* __restrict__ out) {
    const int tid = threadIdx.x;
    const int wid = tid >> 5;
    const int lane = tid & 31;
    const int warp_m = wid >> 1;            // 0..3 (32 rows each)
    const int warp_n = wid & 1;             // 0..1 (64 cols each)
    const int split = blockIdx.x;
    const int rowBase = blockIdx.y * TM;
    const int colBase0 = split * CPS;

    const u32 sbase = smem_u32(smem);

    // ---- group 0: A chunk 0 + B chunk 0 (cp.async) ----
#pragma unroll
    for (int i = 0; i < 4; i++) {
        const int f = tid + i * 256;        // 0..1023
        const int r = f >> 3;
        const int g = f & 7;
        cp_async16(sbase + SA + r * A_STRIDE + g * 16,
                   g_qh + (size_t)(rowBase + r) * CC + g * 8);
    }
#pragma unroll
    for (int i = 0; i < 4; i++) {
        const int f = tid + i * 256;
        const int r = f >> 3;
        const int g = f & 7;
        cp_async16(sbase + SB + r * B_STRIDE + g * 16,
                   g_kh + (size_t)(colBase0 + r) * CC + g * 8);
    }
    cp_commit();

    // ---- group 1: A chunks 1..3 (land under chunk-0 compute) ----
#pragma unroll
    for (int c = 1; c < 4; c++) {
#pragma unroll
        for (int i = 0; i < 4; i++) {
            const int f = tid + i * 256;
            const int r = f >> 3;
            const int g = f & 7;
            cp_async16(sbase + SA + r * A_STRIDE + (c * 8 + g) * 16,
                       g_qh + (size_t)(rowBase + r) * CC + c * KCH + g * 8);
        }
    }
    cp_commit();

    cp_wait1();                 // waits group 0 only (FIFO)
    __syncthreads();

    float acc[2][8][4];
#pragma unroll
    for (int mt = 0; mt < 2; mt++)
#pragma unroll
        for (int no = 0; no < 8; no++)
#pragma unroll
            for (int x = 0; x < 4; x++) acc[mt][no][x] = 0.0f;

    float rm[4], rs[4];
#pragma unroll
    for (int s = 0; s < 4; s++) { rm[s] = -CUDART_INF_F; rs[s] = 0.0f; }

    const u32 a_lane = (u32)((warp_m * 32 + (lane & 15)) * A_STRIDE + (lane >> 4) * 16);
    const u32 b_lane = (u32)((warp_n * 64 + (lane >> 4) * 8 + (lane & 7)) * B_STRIDE
                             + ((lane >> 3) & 1) * 16);

    for (int t = 0; t < NCHUNKS; t++) {
        const u32 bs = sbase + SB + (t & 1) * SB_STAGE;

        if (t + 1 < NCHUNKS) {
            const int nt = (t + 1) >> 2;
            const int nc = (t + 1) & 3;
            const int colBase = colBase0 + nt * TNT;
            const u32 bd = sbase + SB + ((t + 1) & 1) * SB_STAGE;
#pragma unroll
            for (int i = 0; i < 4; i++) {
                const int f = tid + i * 256;
                const int r = f >> 3;
                const int g = f & 7;
                cp_async16(bd + r * B_STRIDE + g * 16,
                           g_kh + (size_t)(colBase + r) * CC + nc * KCH + g * 8);
            }
            cp_commit();
        }

        const int kc = (t & 3) * KCH;
#pragma unroll
        for (int ks = 0; ks < 4; ks++) {
            u32 a[2][4], b[4][4];
#pragma unroll
            for (int mt = 0; mt < 2; mt++)
                ldsm_x4(a[mt][0], a[mt][1], a[mt][2], a[mt][3],
                        sbase + SA + a_lane + (u32)(mt * 16 * A_STRIDE + (kc + ks * 16) * 2));
#pragma unroll
            for (int nt = 0; nt < 4; nt++)
                ldsm_x4(b[nt][0], b[nt][1], b[nt][2], b[nt][3],
                        bs + b_lane + (u32)(nt * 16 * B_STRIDE + ks * 32));
#pragma unroll
            for (int mt = 0; mt < 2; mt++)
#pragma unroll
                for (int no = 0; no < 8; no++) {
                    const int bt = no >> 1, pr = no & 1;
                    mma16816(acc[mt][no][0], acc[mt][no][1], acc[mt][no][2], acc[mt][no][3],
                             a[mt][0], a[mt][1], a[mt][2], a[mt][3],
                             b[bt][pr * 2], b[bt][pr * 2 + 1]);
                }
        }

        // ---- tile finished: fp16-SIMD online LSE (acc in log2 units) ----
        if ((t & 3) == 3) {
#pragma unroll
            for (int mt = 0; mt < 2; mt++) {
#pragma unroll
                for (int h = 0; h < 2; h++) {
                    const int s = mt * 2 + h;
                    __half2 x2[8];
#pragma unroll
                    for (int no = 0; no < 8; no++)
                        x2[no] = __floats2half2_rn(acc[mt][no][h * 2 + 0],
                                                   acc[mt][no][h * 2 + 1]);
                    __half2 m2 = __hmax2(__hmax2(__hmax2(x2[0], x2[1]), __hmax2(x2[2], x2[3])),
                                         __hmax2(__hmax2(x2[4], x2[5]), __hmax2(x2[6], x2[7])));
                    const float mloc = __half2float(__hmax(__low2half(m2), __high2half(m2)));
                    const float mn = fmaxf(rm[s], mloc);     // exactly fp16-representable
                    const __half2 mn2 = __float2half2_rn(mn);
                    __half2 s2 = h2exp2(__hsub2(x2[0], mn2));
                    __half2 s2b = h2exp2(__hsub2(x2[1], mn2));
#pragma unroll
                    for (int no = 2; no < 8; no += 2) {
                        s2 = __hadd2(s2, h2exp2(__hsub2(x2[no], mn2)));
                        s2b = __hadd2(s2b, h2exp2(__hsub2(x2[no + 1], mn2)));
                    }
                    s2 = __hadd2(s2, s2b);
                    const float bsm = __half2float(__low2half(s2)) + __half2float(__high2half(s2));
                    rs[s] = rs[s] * exp2f(rm[s] - mn) + bsm;
                    rm[s] = mn;
                }
#pragma unroll
                for (int no = 0; no < 8; no++)
#pragma unroll
                    for (int xx = 0; xx < 4; xx++) acc[mt][no][xx] = 0.0f;
            }
        }

        cp_wait0();
        __syncthreads();
    }

    // ---- merge across the 4 lanes sharing each row ----
#pragma unroll
    for (int s = 0; s < 4; s++) {
#pragma unroll
        for (int off = 1; off <= 2; off <<= 1) {
            const float om = __shfl_xor_sync(0xFFFFFFFFu, rm[s], off);
            const float os = __shfl_xor_sync(0xFFFFFFFFu, rs[s], off);
            const float nm = fmaxf(rm[s], om);
            rs[s] = rs[s] * exp2f(rm[s] - nm) + os * exp2f(om - nm);
            rm[s] = nm;
        }
    }

    // ---- cross-warp reduce + store split partials (log2 domain) ----
    float* redm = (float*)(smem + SRED_M);
    float* reds = (float*)(smem + SRED_S);
    if ((lane & 3) == 0) {
#pragma unroll
        for (int mt = 0; mt < 2; mt++)
#pragma unroll
            for (int h = 0; h < 2; h++) {
                const int row = warp_m * 32 + mt * 16 + h * 8 + (lane >> 2);
                redm[row * 2 + warp_n] = rm[mt * 2 + h];
                reds[row * 2 + warp_n] = rs[mt * 2 + h];
            }
    }
    __syncthreads();
    if (tid < TM) {
        const float m0 = redm[tid * 2], m1 = redm[tid * 2 + 1];
        const float mg = fmaxf(m0, m1);
        const float sg = reds[tid * 2] * exp2f(m0 - mg) + reds[tid * 2 + 1] * exp2f(m1 - mg);
        g_pm[(rowBase + tid) * NSPLIT + split] = mg;
        g_ps[(rowBase + tid) * NSPLIT + split] = sg;
    }

    // ---- ticket: last CTA performs the deterministic final combine ----
    __shared__ bool amLast;
    __syncthreads();
    if (tid == 0) {
        __threadfence();
        const unsigned int tk = atomicAdd(&g_ticket, 1u);
        amLast = (tk == NCTAS - 1u);
    }
    __syncthreads();
    if (amLast) {
        __threadfence();
        float tot = 0.0f;
#pragma unroll 4
        for (int blk = 0; blk < NN / 256; blk++) {      // fixed order per thread
            const int r = blk * 256 + tid;
            const float4 pm = *(const float4*)(g_pm + r * NSPLIT);
            const float4 ps = *(const float4*)(g_ps + r * NSPLIT);
            const float mg = fmaxf(fmaxf(pm.x, pm.y), fmaxf(pm.z, pm.w));
            const float sg = ps.x * exp2f(pm.x - mg) + ps.y * exp2f(pm.y - mg)
                           + ps.z * exp2f(pm.z - mg) + ps.w * exp2f(pm.w - mg);
            tot += LN2 * (mg + log2f(sg)) - g_pos[r];
        }
        float* red = (float*)(smem + SRED_M);
        red[tid] = tot;
        __syncthreads();
        for (int o = 128; o; o >>= 1) {
            if (tid < o) red[tid] += red[tid + o];
            __syncthreads();
        }
        if (tid == 0) {
            out[0] = red[0] / (float)NN;
            g_ticket = 0u;      // reset for next graph replay
        }
    }
}

// ---------------------------------------------------------------------------
extern "C" void kernel_launch(void* const* d_in, const int* in_sizes, int n_in,
                              void* d_out, int out_size) {
    const float* q = (const float*)d_in[0];
    const float* k = (const float*)d_in[1];
    float* out = (float*)d_out;

    cudaFuncSetAttribute(sim_lse_hmma_kernel,
                         cudaFuncAttributeMaxDynamicSharedMemorySize, SM_TOTAL);

    convert_pos_kernel<<<NN * 32 / 256, 256>>>(q, k);
    dim3 grid(NSPLIT, NN / TM);
    sim_lse_hmma_kernel<<<grid, 256, SM_TOTAL>>>(out);
}

// round 7
// speedup vs baseline: 1.5795x; 1.5795x over previous
#include <cuda_runtime.h>
#include <cuda_fp16.h>
#include <math_constants.h>

// ---------------------------------------------------------------------------
// Problem constants
// ---------------------------------------------------------------------------
#define NN 8192
#define CC 256
#define TM 128                  // CTA rows
#define TNT 128                 // CTA col-tile width
#define NSPLIT 4
#define CPS (NN / NSPLIT)       // 2048 cols per CTA
#define NTILE (CPS / TNT)       // 16 col tiles
#define KCH 64                  // k per chunk
#define NCHUNKS (NTILE * 4)     // 64 chunk steps
#define INV_T 14.285714285714285714f
#define LN2 0.6931471805599453f
// sqrt(INV_T * log2(e)) folded into fp16 operands: acc = logit * log2(e)
#define SCALE 4.5398160052f

// SMEM layout (dynamic)
#define A_STRIDE 528            // 256 halves + 8 pad
#define B_STRIDE 144            // 64 halves + 8 pad
#define SA 0
#define SA_BYTES (TM * A_STRIDE)            // 67584
#define SB (SA + SA_BYTES)
#define SB_STAGE (TNT * B_STRIDE)           // 18432
#define SRED_M (SB + 2 * SB_STAGE)          // 104448
#define SRED_S (SRED_M + TM * 2 * 4)        // +1024
#define SM_TOTAL (SRED_S + TM * 2 * 4)      // 106496  (x2 CTAs = 212992 < 228KB)

typedef unsigned int u32;

// ---------------------------------------------------------------------------
// Device globals (no allocation allowed)
// ---------------------------------------------------------------------------
__device__ __align__(16) __half g_qh[NN * CC];
__device__ __align__(16) __half g_kh[NN * CC];
__device__ float g_pm[NN * NSPLIT];
__device__ float g_ps[NN * NSPLIT];
__device__ float g_pos[NN];
__device__ float g_part[32];
__device__ unsigned int g_ticket;   // zero-initialized; reset by last block

// ---------------------------------------------------------------------------
// PTX helpers (base ISA only; must compile for compute_103 non-'a')
// ---------------------------------------------------------------------------
__device__ __forceinline__ u32 smem_u32(const void* p) {
    u32 a;
    asm("{ .reg .u64 t; cvta.to.shared.u64 t, %1; cvt.u32.u64 %0, t; }" : "=r"(a) : "l"(p));
    return a;
}
__device__ __forceinline__ void cp_async16(u32 dst, const void* src) {
    asm volatile("cp.async.cg.shared.global [%0], [%1], 16;" :: "r"(dst), "l"(src));
}
__device__ __forceinline__ void cp_commit() {
    asm volatile("cp.async.commit_group;" ::: "memory");
}
__device__ __forceinline__ void cp_wait0() {
    asm volatile("cp.async.wait_group 0;" ::: "memory");
}
__device__ __forceinline__ void cp_wait1() {
    asm volatile("cp.async.wait_group 1;" ::: "memory");
}
__device__ __forceinline__ void ldsm_x4(u32& r0, u32& r1, u32& r2, u32& r3, u32 addr) {
    asm volatile("ldmatrix.sync.aligned.m8n8.x4.shared.b16 {%0,%1,%2,%3}, [%4];"
                 : "=r"(r0), "=r"(r1), "=r"(r2), "=r"(r3) : "r"(addr));
}
__device__ __forceinline__ void mma16816(float& d0, float& d1, float& d2, float& d3,
                                         u32 a0, u32 a1, u32 a2, u32 a3,
                                         u32 b0, u32 b1) {
    asm volatile("mma.sync.aligned.m16n8k16.row.col.f32.f16.f16.f32 "
                 "{%0,%1,%2,%3}, {%4,%5,%6,%7}, {%8,%9}, {%0,%1,%2,%3};"
                 : "+f"(d0), "+f"(d1), "+f"(d2), "+f"(d3)
                 : "r"(a0), "r"(a1), "r"(a2), "r"(a3), "r"(b0), "r"(b1));
}

// ---------------------------------------------------------------------------
// Fused convert (fp32 -> scaled fp16) + diagonal dot. One warp per row.
// Front-batched loads (MLP=4) — kernel is DRAM-latency bound.
// ---------------------------------------------------------------------------
__global__ void convert_pos_kernel(const float* __restrict__ q, const float* __restrict__ k) {
    const int row = (blockIdx.x * blockDim.x + threadIdx.x) >> 5;
    const int lane = threadIdx.x & 31;
    const float4* q4 = (const float4*)(q + (size_t)row * CC);
    const float4* k4 = (const float4*)(k + (size_t)row * CC);
    const float4 a0 = q4[lane];
    const float4 a1 = q4[lane + 32];
    const float4 b0 = k4[lane];
    const float4 b1 = k4[lane + 32];

    float dot = (a0.x * b0.x + a0.y * b0.y) + (a0.z * b0.z + a0.w * b0.w)
              + (a1.x * b1.x + a1.y * b1.y) + (a1.z * b1.z + a1.w * b1.w);

    uint2 o;
    __half2 h;
    h = __floats2half2_rn(a0.x * SCALE, a0.y * SCALE); o.x = *(u32*)&h;
    h = __floats2half2_rn(a0.z * SCALE, a0.w * SCALE); o.y = *(u32*)&h;
    ((uint2*)g_qh)[(size_t)row * (CC / 4) + lane] = o;
    h = __floats2half2_rn(a1.x * SCALE, a1.y * SCALE); o.x = *(u32*)&h;
    h = __floats2half2_rn(a1.z * SCALE, a1.w * SCALE); o.y = *(u32*)&h;
    ((uint2*)g_qh)[(size_t)row * (CC / 4) + lane + 32] = o;
    h = __floats2half2_rn(b0.x * SCALE, b0.y * SCALE); o.x = *(u32*)&h;
    h = __floats2half2_rn(b0.z * SCALE, b0.w * SCALE); o.y = *(u32*)&h;
    ((uint2*)g_kh)[(size_t)row * (CC / 4) + lane] = o;
    h = __floats2half2_rn(b1.x * SCALE, b1.y * SCALE); o.x = *(u32*)&h;
    h = __floats2half2_rn(b1.z * SCALE, b1.w * SCALE); o.y = *(u32*)&h;
    ((uint2*)g_kh)[(size_t)row * (CC / 4) + lane + 32] = o;

#pragma unroll
    for (int off = 16; off; off >>= 1)
        dot += __shfl_xor_sync(0xFFFFFFFFu, dot, off);
    if (lane == 0) g_pos[row] = dot * INV_T;
}

// ---------------------------------------------------------------------------
// Main: HMMA fp16 GEMM fused with online row LSE (log2 domain).
// grid = (NSPLIT=4, 64) = 256 CTAs, 256 threads, 2 CTAs/SM.
// 8 warps: 4 m-groups x 2 n-groups, warp tile 32x64.
// No fused combine tail (it caused register spills in R6).
// ---------------------------------------------------------------------------
extern __shared__ char smem[];

__global__ __launch_bounds__(256, 2)
void sim_lse_hmma_kernel() {
    const int tid = threadIdx.x;
    const int wid = tid >> 5;
    const int lane = tid & 31;
    const int warp_m = wid >> 1;            // 0..3 (32 rows each)
    const int warp_n = wid & 1;             // 0..1 (64 cols each)
    const int split = blockIdx.x;
    const int rowBase = blockIdx.y * TM;
    const int colBase0 = split * CPS;

    const u32 sbase = smem_u32(smem);

    // ---- group 0: A chunk 0 + B chunk 0 (cp.async) ----
#pragma unroll
    for (int i = 0; i < 4; i++) {
        const int f = tid + i * 256;        // 0..1023
        const int r = f >> 3;
        const int g = f & 7;
        cp_async16(sbase + SA + r * A_STRIDE + g * 16,
                   g_qh + (size_t)(rowBase + r) * CC + g * 8);
    }
#pragma unroll
    for (int i = 0; i < 4; i++) {
        const int f = tid + i * 256;
        const int r = f >> 3;
        const int g = f & 7;
        cp_async16(sbase + SB + r * B_STRIDE + g * 16,
                   g_kh + (size_t)(colBase0 + r) * CC + g * 8);
    }
    cp_commit();

    // ---- group 1: A chunks 1..3 (land under chunk-0 compute) ----
#pragma unroll
    for (int c = 1; c < 4; c++) {
#pragma unroll
        for (int i = 0; i < 4; i++) {
            const int f = tid + i * 256;
            const int r = f >> 3;
            const int g = f & 7;
            cp_async16(sbase + SA + r * A_STRIDE + (c * 8 + g) * 16,
                       g_qh + (size_t)(rowBase + r) * CC + c * KCH + g * 8);
        }
    }
    cp_commit();

    cp_wait1();                 // waits group 0 only (FIFO)
    __syncthreads();

    float acc[2][8][4];
#pragma unroll
    for (int mt = 0; mt < 2; mt++)
#pragma unroll
        for (int no = 0; no < 8; no++)
#pragma unroll
            for (int x = 0; x < 4; x++) acc[mt][no][x] = 0.0f;

    float rm[4], rs[4];
#pragma unroll
    for (int s = 0; s < 4; s++) { rm[s] = -CUDART_INF_F; rs[s] = 0.0f; }

    const u32 a_lane = (u32)((warp_m * 32 + (lane & 15)) * A_STRIDE + (lane >> 4) * 16);
    const u32 b_lane = (u32)((warp_n * 64 + (lane >> 4) * 8 + (lane & 7)) * B_STRIDE
                             + ((lane >> 3) & 1) * 16);

    for (int t = 0; t < NCHUNKS; t++) {
        const u32 bs = sbase + SB + (t & 1) * SB_STAGE;

        if (t + 1 < NCHUNKS) {
            const int nt = (t + 1) >> 2;
            const int nc = (t + 1) & 3;
            const int colBase = colBase0 + nt * TNT;
            const u32 bd = sbase + SB + ((t + 1) & 1) * SB_STAGE;
#pragma unroll
            for (int i = 0; i < 4; i++) {
                const int f = tid + i * 256;
                const int r = f >> 3;
                const int g = f & 7;
                cp_async16(bd + r * B_STRIDE + g * 16,
                           g_kh + (size_t)(colBase + r) * CC + nc * KCH + g * 8);
            }
            cp_commit();
        }

        const int kc = (t & 3) * KCH;
#pragma unroll
        for (int ks = 0; ks < 4; ks++) {
            u32 a[2][4], b[4][4];
#pragma unroll
            for (int mt = 0; mt < 2; mt++)
                ldsm_x4(a[mt][0], a[mt][1], a[mt][2], a[mt][3],
                        sbase + SA + a_lane + (u32)(mt * 16 * A_STRIDE + (kc + ks * 16) * 2));
#pragma unroll
            for (int nt = 0; nt < 4; nt++)
                ldsm_x4(b[nt][0], b[nt][1], b[nt][2], b[nt][3],
                        bs + b_lane + (u32)(nt * 16 * B_STRIDE + ks * 32));
#pragma unroll
            for (int mt = 0; mt < 2; mt++)
#pragma unroll
                for (int no = 0; no < 8; no++) {
                    const int bt = no >> 1, pr = no & 1;
                    mma16816(acc[mt][no][0], acc[mt][no][1], acc[mt][no][2], acc[mt][no][3],
                             a[mt][0], a[mt][1], a[mt][2], a[mt][3],
                             b[bt][pr * 2], b[bt][pr * 2 + 1]);
                }
        }

        // ---- tile finished: fp16-SIMD online LSE (acc in log2 units) ----
        if ((t & 3) == 3) {
#pragma unroll
            for (int mt = 0; mt < 2; mt++) {
#pragma unroll
                for (int h = 0; h < 2; h++) {
                    const int s = mt * 2 + h;
                    __half2 x2[8];
#pragma unroll
                    for (int no = 0; no < 8; no++)
                        x2[no] = __floats2half2_rn(acc[mt][no][h * 2 + 0],
                                                   acc[mt][no][h * 2 + 1]);
                    __half2 m2 = __hmax2(__hmax2(__hmax2(x2[0], x2[1]), __hmax2(x2[2], x2[3])),
                                         __hmax2(__hmax2(x2[4], x2[5]), __hmax2(x2[6], x2[7])));
                    const float mloc = __half2float(__hmax(__low2half(m2), __high2half(m2)));
                    const float mn = fmaxf(rm[s], mloc);     // exactly fp16-representable
                    const __half2 mn2 = __float2half2_rn(mn);
                    __half2 s2 = h2exp2(__hsub2(x2[0], mn2));
                    __half2 s2b = h2exp2(__hsub2(x2[1], mn2));
#pragma unroll
                    for (int no = 2; no < 8; no += 2) {
                        s2 = __hadd2(s2, h2exp2(__hsub2(x2[no], mn2)));
                        s2b = __hadd2(s2b, h2exp2(__hsub2(x2[no + 1], mn2)));
                    }
                    s2 = __hadd2(s2, s2b);
                    const float bsm = __half2float(__low2half(s2)) + __half2float(__high2half(s2));
                    rs[s] = rs[s] * exp2f(rm[s] - mn) + bsm;
                    rm[s] = mn;
                }
#pragma unroll
                for (int no = 0; no < 8; no++)
#pragma unroll
                    for (int xx = 0; xx < 4; xx++) acc[mt][no][xx] = 0.0f;
            }
        }

        cp_wait0();
        __syncthreads();
    }

    // ---- merge across the 4 lanes sharing each row ----
#pragma unroll
    for (int s = 0; s < 4; s++) {
#pragma unroll
        for (int off = 1; off <= 2; off <<= 1) {
            const float om = __shfl_xor_sync(0xFFFFFFFFu, rm[s], off);
            const float os = __shfl_xor_sync(0xFFFFFFFFu, rs[s], off);
            const float nm = fmaxf(rm[s], om);
            rs[s] = rs[s] * exp2f(rm[s] - nm) + os * exp2f(om - nm);
            rm[s] = nm;
        }
    }

    // ---- cross-warp reduce (2 warp_n groups) + store split partials ----
    float* redm = (float*)(smem + SRED_M);
    float* reds = (float*)(smem + SRED_S);
    if ((lane & 3) == 0) {
#pragma unroll
        for (int mt = 0; mt < 2; mt++)
#pragma unroll
            for (int h = 0; h < 2; h++) {
                const int row = warp_m * 32 + mt * 16 + h * 8 + (lane >> 2);
                redm[row * 2 + warp_n] = rm[mt * 2 + h];
                reds[row * 2 + warp_n] = rs[mt * 2 + h];
            }
    }
    __syncthreads();
    if (tid < TM) {
        const float m0 = redm[tid * 2], m1 = redm[tid * 2 + 1];
        const float mg = fmaxf(m0, m1);
        const float sg = reds[tid * 2] * exp2f(m0 - mg) + reds[tid * 2 + 1] * exp2f(m1 - mg);
        g_pm[(rowBase + tid) * NSPLIT + split] = mg;
        g_ps[(rowBase + tid) * NSPLIT + split] = sg;
    }
}

// ---------------------------------------------------------------------------
// Combine (single launch): 32 blocks reduce 256 rows each; the last block to
// finish sums the 32 partials in fixed order (deterministic) and writes out.
// ---------------------------------------------------------------------------
__global__ void combine_kernel(float* __restrict__ out) {
    __shared__ float red[256];
    __shared__ bool amLast;
    const int r = blockIdx.x * 256 + threadIdx.x;
    const float4 pm = *(const float4*)(g_pm + r * NSPLIT);
    const float4 ps = *(const float4*)(g_ps + r * NSPLIT);
    const float mg = fmaxf(fmaxf(pm.x, pm.y), fmaxf(pm.z, pm.w));
    const float sg = ps.x * exp2f(pm.x - mg) + ps.y * exp2f(pm.y - mg)
                   + ps.z * exp2f(pm.z - mg) + ps.w * exp2f(pm.w - mg);
    red[threadIdx.x] = LN2 * (mg + log2f(sg)) - g_pos[r];
    __syncthreads();
    for (int o = 128; o; o >>= 1) {
        if (threadIdx.x < o) red[threadIdx.x] += red[threadIdx.x + o];
        __syncthreads();
    }
    if (threadIdx.x == 0) {
        g_part[blockIdx.x] = red[0];
        __threadfence();
        const unsigned int t = atomicAdd(&g_ticket, 1u);
        amLast = (t == 31u);
    }
    __syncthreads();
    if (amLast && threadIdx.x == 0) {
        float tot = 0.0f;
#pragma unroll
        for (int i = 0; i < 32; i++) tot += g_part[i];
        out[0] = tot / (float)NN;
        g_ticket = 0u;   // reset for next graph replay
    }
}

// ---------------------------------------------------------------------------
extern "C" void kernel_launch(void* const* d_in, const int* in_sizes, int n_in,
                              void* d_out, int out_size) {
    const float* q = (const float*)d_in[0];
    const float* k = (const float*)d_in[1];
    float* out = (float*)d_out;

    cudaFuncSetAttribute(sim_lse_hmma_kernel,
                         cudaFuncAttributeMaxDynamicSharedMemorySize, SM_TOTAL);

    convert_pos_kernel<<<NN * 32 / 256, 256>>>(q, k);
    dim3 grid(NSPLIT, NN / TM);
    sim_lse_hmma_kernel<<<grid, 256, SM_TOTAL>>>();
    combine_kernel<<<32, 256>>>(out);
}